// round 16
// baseline (speedup 1.0000x reference)
#include <cuda_runtime.h>
#include <cuda_fp16.h>
#include <math.h>

// Problem constants
#define Bb 2
#define Ss 2048
#define DM 1024
#define Hh 16
#define DKh 64
#define MTOK (Bb*Ss)                 // 4096
#define NROWS (Bb*Hh*Ss)             // 65536
#define OUT_ELEMS ((size_t)Bb*Ss*DM)

#define SCALE_L2E 0.18033688011112042f   // 0.125 * log2(e)

typedef unsigned int u32;
typedef unsigned short u16;
typedef unsigned long long u64;

// ---------------- device scratch ----------------
__device__ __half g_qi_h[MTOK*DM], g_qi_l[MTOK*DM];
__device__ __half g_ki_h[MTOK*DM], g_ki_l[MTOK*DM];
__device__ __half g_vi_h[MTOK*DM], g_vi_l[MTOK*DM];
__device__ __half g_wq_h[DM*DM];
__device__ __half g_wk_h[DM*DM];
__device__ __half g_wv_h[DM*DM];
__device__ __half g_wo_h[DM*DM];
__device__ __half g_qh_h[MTOK*DM], g_qh_l[MTOK*DM];
__device__ __half g_kh_h[MTOK*DM];
__device__ __half g_vh_h[MTOK*DM];
__device__ __half g_oh_h[MTOK*DM], g_oh_l[MTOK*DM];
__device__ float  g_y[MTOK*DM];
__device__ float  g_rinv[NROWS];
__device__ u64    g_mbits[(size_t)Bb*Ss*(Ss/64)];   // 1 bit per mask byte

// ---------------- helpers ----------------
__device__ __forceinline__ u32 smaddr(const void* p) {
    return (u32)__cvta_generic_to_shared(p);
}
__device__ __forceinline__ void ldsm4(u32& r0, u32& r1, u32& r2, u32& r3, u32 a) {
    asm volatile("ldmatrix.sync.aligned.m8n8.x4.shared.b16 {%0,%1,%2,%3},[%4];"
                 : "=r"(r0), "=r"(r1), "=r"(r2), "=r"(r3) : "r"(a));
}
__device__ __forceinline__ void ldsm4t(u32& r0, u32& r1, u32& r2, u32& r3, u32 a) {
    asm volatile("ldmatrix.sync.aligned.m8n8.x4.trans.shared.b16 {%0,%1,%2,%3},[%4];"
                 : "=r"(r0), "=r"(r1), "=r"(r2), "=r"(r3) : "r"(a));
}
__device__ __forceinline__ void mma16(float* d, const u32* a, u32 b0, u32 b1) {
    asm volatile(
        "mma.sync.aligned.m16n8k16.row.col.f32.f16.f16.f32 "
        "{%0,%1,%2,%3},{%4,%5,%6,%7},{%8,%9},{%0,%1,%2,%3};"
        : "+f"(d[0]), "+f"(d[1]), "+f"(d[2]), "+f"(d[3])
        : "r"(a[0]), "r"(a[1]), "r"(a[2]), "r"(a[3]), "r"(b0), "r"(b1));
}
__device__ __forceinline__ void cpa16(u32 dst, const void* src) {
    asm volatile("cp.async.cg.shared.global [%0], [%1], 16;" :: "r"(dst), "l"(src));
}
#define CP_COMMIT() asm volatile("cp.async.commit_group;")
#define CP_WAIT1()  asm volatile("cp.async.wait_group 1;")
#define CP_WAIT0()  asm volatile("cp.async.wait_group 0;")
__device__ __forceinline__ float ex2f(float x) {
    float r; asm("ex2.approx.f32 %0, %1;" : "=f"(r) : "f"(x)); return r;
}
__device__ __forceinline__ void stcs2(float* p, float x, float y) {
    asm volatile("st.global.cs.v2.f32 [%0], {%1,%2};" :: "l"(p), "f"(x), "f"(y) : "memory");
}

// ---------------- mask -> bitmask (1 bit per byte) ----------------
__global__ void __launch_bounds__(256)
mask_bits(const unsigned char* __restrict__ mask)
{
    int i = blockIdx.x * 256 + threadIdx.x;
    const u64* src = (const u64*)(mask + (size_t)i * 64);
    u64 bits = 0;
    #pragma unroll
    for (int c = 0; c < 8; ++c) {
        u64 w = src[c] & 0x0101010101010101ULL;
        bits |= ((w * 0x0102040810204080ULL) >> 56) << (c * 8);
    }
    g_mbits[i] = bits;
}

// ---------------- merged split kernels ----------------
__global__ void __launch_bounds__(256)
split_f32x3(const float* __restrict__ s0, __half* __restrict__ h0, __half* __restrict__ l0,
            const float* __restrict__ s1, __half* __restrict__ h1, __half* __restrict__ l1,
            const float* __restrict__ s2, __half* __restrict__ h2, __half* __restrict__ l2)
{
    int i = blockIdx.x * 256 + threadIdx.x;
    const float* src; __half* dh; __half* dl;
    if (blockIdx.y == 0)      { src = s0; dh = h0; dl = l0; }
    else if (blockIdx.y == 1) { src = s1; dh = h1; dl = l1; }
    else                      { src = s2; dh = h2; dl = l2; }
    float4 v = ((const float4*)src)[i];
    __half2 a0 = __floats2half2_rn(v.x, v.y);
    __half2 a1 = __floats2half2_rn(v.z, v.w);
    float2 f0 = __half22float2(a0), f1 = __half22float2(a1);
    ((__half2*)dh)[2*i]   = a0; ((__half2*)dh)[2*i+1] = a1;
    ((__half2*)dl)[2*i]   = __floats2half2_rn(v.x - f0.x, v.y - f0.y);
    ((__half2*)dl)[2*i+1] = __floats2half2_rn(v.z - f1.x, v.w - f1.y);
}

__global__ void __launch_bounds__(256)
splitT_w4(const float* __restrict__ W0, __half* __restrict__ th0,
          const float* __restrict__ W1, __half* __restrict__ th1,
          const float* __restrict__ W2, __half* __restrict__ th2,
          const float* __restrict__ W3, __half* __restrict__ th3)
{
    const float* W; __half* th;
    switch (blockIdx.z) {
        case 0:  W = W0; th = th0; break;
        case 1:  W = W1; th = th1; break;
        case 2:  W = W2; th = th2; break;
        default: W = W3; th = th3; break;
    }
    __shared__ float t[32][33];
    int kb = blockIdx.y * 32, nb = blockIdx.x * 32;
    int tx = threadIdx.x, ty = threadIdx.y;
    #pragma unroll
    for (int i = 0; i < 4; ++i)
        t[ty + i*8][tx] = W[(size_t)(kb + ty + i*8) * DM + nb + tx];
    __syncthreads();
    #pragma unroll
    for (int i = 0; i < 4; ++i) {
        int n = nb + ty + i*8, k = kb + tx;
        th[(size_t)n * DM + k] = __float2half_rn(t[tx][ty + i*8]);
    }
}

// ---------------------------------------------------------------------------
// fp16 GEMM core, 2-term: C = (Ah+Al) @ Bh^T (+bias)*omul (+R)
// ---------------------------------------------------------------------------
#define SG 40
#define GARR (128*SG)
#define GSTG (3*GARR)
__device__ __forceinline__ void
gemm_core(const __half* __restrict__ Ah, const __half* __restrict__ Al,
          const __half* __restrict__ Bh,
          const float* __restrict__ bias, const float* __restrict__ R,
          float omul,
          __half* __restrict__ Ch, __half* __restrict__ Cl,
          float* __restrict__ Cf, int M, int N, int K,
          __half* dsm, int bm, int bn)
{
    const int tid = threadIdx.x, lane = tid & 31, wid = tid >> 5;
    const int wm = wid & 3, wn = wid >> 2;
    float acc[2][8][4] = {};
    const int arow = lane & 15, achk = lane >> 4;
    const int brow = ((lane >> 4) << 3) + (lane & 7), bchk = (lane >> 3) & 1;
    const u32 smbase = smaddr(dsm);

    auto load_stage = [&](int st, int k0) {
        u32 base = smbase + (u32)st * GSTG * 2;
        #pragma unroll
        for (int i = 0; i < 2; ++i) {
            int e = tid + i * 256;
            int m = e >> 2, c = e & 3;
            size_t ga = (size_t)(bm + m) * K + k0 + c*8;
            size_t gb = (size_t)(bn + m) * K + k0 + c*8;
            u32 o = (u32)(m*SG + c*8) * 2;
            cpa16(base + 0*GARR*2 + o, Ah + ga);
            cpa16(base + 1*GARR*2 + o, Al + ga);
            cpa16(base + 2*GARR*2 + o, Bh + gb);
        }
        CP_COMMIT();
    };

    const int nk = K / 32;
    load_stage(0, 0);
    for (int kt = 0; kt < nk; ++kt) {
        if (kt + 1 < nk) { load_stage((kt+1)&1, (kt+1)*32); CP_WAIT1(); }
        else             { CP_WAIT0(); }
        __syncthreads();
        const u32 sAh = smbase + (u32)(kt&1)*GSTG*2;
        const u32 sAl = sAh + GARR*2;
        const u32 sBh = sAl + GARR*2;
        #pragma unroll
        for (int kc = 0; kc < 2; ++kc) {
            u32 ah[2][4], al[2][4];
            #pragma unroll
            for (int mt = 0; mt < 2; ++mt) {
                int row = wm*32 + mt*16 + arow;
                u32 off = row*(SG*2) + (2*kc + achk)*16;
                ldsm4(ah[mt][0],ah[mt][1],ah[mt][2],ah[mt][3], sAh+off);
                ldsm4(al[mt][0],al[mt][1],al[mt][2],al[mt][3], sAl+off);
            }
            #pragma unroll
            for (int ntp = 0; ntp < 4; ++ntp) {
                int row = wn*64 + ntp*16 + brow;
                u32 off = row*(SG*2) + (2*kc + bchk)*16;
                u32 b0,b1,b2,b3;
                ldsm4(b0,b1,b2,b3, sBh+off);
                mma16(acc[0][2*ntp],   ah[0], b0, b1);
                mma16(acc[1][2*ntp],   ah[1], b0, b1);
                mma16(acc[0][2*ntp+1], ah[0], b2, b3);
                mma16(acc[1][2*ntp+1], ah[1], b2, b3);
                mma16(acc[0][2*ntp],   al[0], b0, b1);
                mma16(acc[1][2*ntp],   al[1], b0, b1);
                mma16(acc[0][2*ntp+1], al[0], b2, b3);
                mma16(acc[1][2*ntp+1], al[1], b2, b3);
            }
        }
        __syncthreads();
    }

    #pragma unroll
    for (int mt = 0; mt < 2; ++mt) {
        int r0 = bm + wm*32 + mt*16 + (lane >> 2);
        #pragma unroll
        for (int nt = 0; nt < 8; ++nt) {
            int n = bn + wn*64 + nt*8 + (lane & 3)*2;
            float2 bs = *(const float2*)&bias[n];
            float* d = acc[mt][nt];
            float v00 = (d[0]+bs.x)*omul, v01 = (d[1]+bs.y)*omul;
            float v10 = (d[2]+bs.x)*omul, v11 = (d[3]+bs.y)*omul;
            if (Cf) {
                float2 ra = *(const float2*)&R[(size_t)r0*N + n];
                float2 rb = *(const float2*)&R[(size_t)(r0+8)*N + n];
                *(float2*)&Cf[(size_t)r0*N + n]     = make_float2(v00+ra.x, v01+ra.y);
                *(float2*)&Cf[(size_t)(r0+8)*N + n] = make_float2(v10+rb.x, v11+rb.y);
            } else if (Cl) {
                __half2 h0 = __floats2half2_rn(v00, v01);
                __half2 h1 = __floats2half2_rn(v10, v11);
                float2 f0 = __half22float2(h0), f1 = __half22float2(h1);
                *(__half2*)&Ch[(size_t)r0*N + n]     = h0;
                *(__half2*)&Ch[(size_t)(r0+8)*N + n] = h1;
                *(__half2*)&Cl[(size_t)r0*N + n]     = __floats2half2_rn(v00-f0.x, v01-f0.y);
                *(__half2*)&Cl[(size_t)(r0+8)*N + n] = __floats2half2_rn(v10-f1.x, v11-f1.y);
            } else {
                *(__half2*)&Ch[(size_t)r0*N + n]     = __floats2half2_rn(v00, v01);
                *(__half2*)&Ch[(size_t)(r0+8)*N + n] = __floats2half2_rn(v10, v11);
            }
        }
    }
}

// Out-projection wrapper
__global__ void __launch_bounds__(256)
gemm_h3(const __half* __restrict__ Ah, const __half* __restrict__ Al,
        const __half* __restrict__ Bh,
        const float* __restrict__ bias, const float* __restrict__ R,
        float omul,
        __half* __restrict__ Ch, __half* __restrict__ Cl,
        float* __restrict__ Cf, int M, int N, int K)
{
    extern __shared__ __half dsm[];
    gemm_core(Ah, Al, Bh, bias, R, omul, Ch, Cl, Cf, M, N, K,
              dsm, blockIdx.y * 128, blockIdx.x * 128);
}

// Q+K projections: grid.z = 0(Q) / 1(K)
__global__ void __launch_bounds__(256)
gemm_qk(const __half* __restrict__ qih, const __half* __restrict__ qil,
        const __half* __restrict__ kih, const __half* __restrict__ kil,
        const __half* __restrict__ wqh, const __half* __restrict__ wkh,
        const float* __restrict__ bq, const float* __restrict__ bk,
        __half* __restrict__ qhh, __half* __restrict__ qhl,
        __half* __restrict__ khh)
{
    extern __shared__ __half dsm[];
    int bm = blockIdx.y * 128, bn = blockIdx.x * 128;
    if (blockIdx.z == 0)
        gemm_core(qih, qil, wqh, bq, nullptr, SCALE_L2E,
                  qhh, qhl, nullptr, MTOK, DM, DM, dsm, bm, bn);
    else
        gemm_core(kih, kil, wkh, bk, nullptr, 1.0f,
                  khh, nullptr, nullptr, MTOK, DM, DM, dsm, bm, bn);
}

// V projection (runs concurrently with pass1 on a side stream)
__global__ void __launch_bounds__(256)
gemm_v(const __half* __restrict__ vih, const __half* __restrict__ vil,
       const __half* __restrict__ wvh, const float* __restrict__ bv,
       __half* __restrict__ vhh)
{
    extern __shared__ __half dsm[];
    gemm_core(vih, vil, wvh, bv, nullptr, 1.0f,
              vhh, nullptr, nullptr, MTOK, DM, DM,
              dsm, blockIdx.y * 128, blockIdx.x * 128);
}

// ---------------------------------------------------------------------------
// Pass 1: row sums of 2^(qh.kh) (masked) — normalizer only.
// ---------------------------------------------------------------------------
#define SP 72
__global__ void __launch_bounds__(512)
attn_pass1()
{
    __shared__ __half sK[2][64*SP];
    const int tid = threadIdx.x, lane = tid & 31, wid = tid >> 5;
    const int bh = blockIdx.y, b = bh >> 4, h = bh & 15;
    const int bq = blockIdx.x * 256;
    const int arow = lane & 15, achk = lane >> 4;
    const int brow = ((lane >> 4) << 3) + (lane & 7), bchk = (lane >> 3) & 1;

    u32 qfh[4][4];
    #pragma unroll
    for (int c = 0; c < 4; ++c) {
        {
            int m = tid >> 3, ch = tid & 7;
            size_t gq = (size_t)(b*Ss + bq + c*64 + m)*DM + h*DKh + ch*8;
            *(uint4*)&sK[0][m*SP + ch*8] = *(const uint4*)&g_qh_h[gq];
        }
        __syncthreads();
        if ((wid >> 2) == c) {
            int rloc = (wid & 3)*16 + arow;
            #pragma unroll
            for (int kc = 0; kc < 4; ++kc) {
                u32 off = rloc*(SP*2) + (2*kc + achk)*16;
                ldsm4(qfh[kc][0],qfh[kc][1],qfh[kc][2],qfh[kc][3], smaddr(sK[0])+off);
            }
        }
        __syncthreads();
    }

    auto load_stage = [&](int st, int kt) {
        int m = tid >> 3, ch = tid & 7;
        size_t gk = (size_t)(b*Ss + kt*64 + m)*DM + h*DKh + ch*8;
        cpa16(smaddr(sK[st]) + (u32)(m*SP + ch*8)*2, g_kh_h + gk);
        CP_COMMIT();
    };

    const int r0 = bq + wid*16 + (lane >> 2);
    float rs0 = 0.f, rs1 = 0.f;

    load_stage(0, 0);
    for (int kt = 0; kt < 32; ++kt) {
        if (kt + 1 < 32) { load_stage((kt+1)&1, kt+1); CP_WAIT1(); }
        else             { CP_WAIT0(); }
        __syncthreads();
        const u32 sKh = smaddr(sK[kt&1]);

        float sf[8][4] = {};
        #pragma unroll
        for (int kc = 0; kc < 4; ++kc) {
            #pragma unroll
            for (int ntp = 0; ntp < 4; ++ntp) {
                int row = ntp*16 + brow;
                u32 off = row*(SP*2) + (2*kc + bchk)*16;
                u32 b0,b1,b2,b3;
                ldsm4(b0,b1,b2,b3, sKh+off);
                mma16(sf[2*ntp],   qfh[kc], b0, b1);
                mma16(sf[2*ntp+1], qfh[kc], b2, b3);
            }
        }
        u64 mb0 = g_mbits[((size_t)b*Ss + r0)*32 + kt];
        u64 mb1 = g_mbits[((size_t)b*Ss + r0 + 8)*32 + kt];
        #pragma unroll
        for (int nt = 0; nt < 8; ++nt) {
            int sh = nt*8 + (lane & 3)*2;
            if (!((mb0 >> sh)     & 1)) rs0 += ex2f(sf[nt][0]);
            if (!((mb0 >> (sh+1)) & 1)) rs0 += ex2f(sf[nt][1]);
            if (!((mb1 >> sh)     & 1)) rs1 += ex2f(sf[nt][2]);
            if (!((mb1 >> (sh+1)) & 1)) rs1 += ex2f(sf[nt][3]);
        }
        __syncthreads();
    }

    rs0 += __shfl_xor_sync(0xffffffffu, rs0, 1);
    rs0 += __shfl_xor_sync(0xffffffffu, rs0, 2);
    rs1 += __shfl_xor_sync(0xffffffffu, rs1, 1);
    rs1 += __shfl_xor_sync(0xffffffffu, rs1, 2);
    if ((lane & 3) == 0) {
        g_rinv[(size_t)bh*Ss + r0]     = 1.0f / rs0;
        g_rinv[(size_t)bh*Ss + r0 + 8] = 1.0f / rs1;
    }
}

// ---------------------------------------------------------------------------
// Pass 2: S = (qh+ql).kh, p = 2^s*inv -> attn (streaming stores); PV fused.
// ---------------------------------------------------------------------------
__global__ void __launch_bounds__(512)
attn_pass2(float* __restrict__ P)
{
    __shared__ __half sKV[2][2][64*SP];
    const int tid = threadIdx.x, lane = tid & 31, wid = tid >> 5;
    const int bh = blockIdx.y, b = bh >> 4, h = bh & 15;
    const int bq = blockIdx.x * 256;
    const int arow = lane & 15, achk = lane >> 4;
    const int brow = ((lane >> 4) << 3) + (lane & 7), bchk = (lane >> 3) & 1;

    u32 qfh[4][4], qfl[4][4];
    #pragma unroll
    for (int c = 0; c < 4; ++c) {
        {
            int m = tid >> 3, ch = tid & 7;
            size_t gq = (size_t)(b*Ss + bq + c*64 + m)*DM + h*DKh + ch*8;
            *(uint4*)&sKV[0][0][m*SP + ch*8] = *(const uint4*)&g_qh_h[gq];
            *(uint4*)&sKV[0][1][m*SP + ch*8] = *(const uint4*)&g_qh_l[gq];
        }
        __syncthreads();
        if ((wid >> 2) == c) {
            int rloc = (wid & 3)*16 + arow;
            #pragma unroll
            for (int kc = 0; kc < 4; ++kc) {
                u32 off = rloc*(SP*2) + (2*kc + achk)*16;
                ldsm4(qfh[kc][0],qfh[kc][1],qfh[kc][2],qfh[kc][3], smaddr(sKV[0][0])+off);
                ldsm4(qfl[kc][0],qfl[kc][1],qfl[kc][2],qfl[kc][3], smaddr(sKV[0][1])+off);
            }
        }
        __syncthreads();
    }

    auto load_stage = [&](int st, int kt) {
        int m = tid >> 3, ch = tid & 7;
        size_t gk = (size_t)(b*Ss + kt*64 + m)*DM + h*DKh + ch*8;
        u32 o = (u32)(m*SP + ch*8)*2;
        cpa16(smaddr(sKV[st][0]) + o, g_kh_h + gk);
        cpa16(smaddr(sKV[st][1]) + o, g_vh_h + gk);
        CP_COMMIT();
    };

    const int r0 = bq + wid*16 + (lane >> 2);
    const float inv0 = g_rinv[(size_t)bh*Ss + r0];
    const float inv1 = g_rinv[(size_t)bh*Ss + r0 + 8];
    float oacc[8][4] = {};

    load_stage(0, 0);
    for (int kt = 0; kt < 32; ++kt) {
        if (kt + 1 < 32) { load_stage((kt+1)&1, kt+1); CP_WAIT1(); }
        else             { CP_WAIT0(); }
        __syncthreads();
        const u32 sKh = smaddr(sKV[kt&1][0]);
        const u32 sVh = smaddr(sKV[kt&1][1]);

        float sf[8][4] = {};
        #pragma unroll
        for (int kc = 0; kc < 4; ++kc) {
            #pragma unroll
            for (int ntp = 0; ntp < 4; ++ntp) {
                int row = ntp*16 + brow;
                u32 off = row*(SP*2) + (2*kc + bchk)*16;
                u32 b0,b1,b2,b3;
                ldsm4(b0,b1,b2,b3, sKh+off);
                mma16(sf[2*ntp],   qfh[kc], b0, b1);
                mma16(sf[2*ntp+1], qfh[kc], b2, b3);
                mma16(sf[2*ntp],   qfl[kc], b0, b1);
                mma16(sf[2*ntp+1], qfl[kc], b2, b3);
            }
        }

        u64 mb0 = g_mbits[((size_t)b*Ss + r0)*32 + kt];
        u64 mb1 = g_mbits[((size_t)b*Ss + r0 + 8)*32 + kt];
        #pragma unroll
        for (int nt = 0; nt < 8; ++nt) {
            int sh = nt*8 + (lane & 3)*2;
            int col = kt*64 + sh;
            float p0 = ((mb0 >> sh)     & 1) ? 0.f : ex2f(sf[nt][0]) * inv0;
            float p1 = ((mb0 >> (sh+1)) & 1) ? 0.f : ex2f(sf[nt][1]) * inv0;
            float p2 = ((mb1 >> sh)     & 1) ? 0.f : ex2f(sf[nt][2]) * inv1;
            float p3 = ((mb1 >> (sh+1)) & 1) ? 0.f : ex2f(sf[nt][3]) * inv1;
            stcs2(&P[((size_t)bh*Ss + r0)*Ss + col],     p0, p1);
            stcs2(&P[((size_t)bh*Ss + r0 + 8)*Ss + col], p2, p3);
            sf[nt][0] = p0; sf[nt][1] = p1; sf[nt][2] = p2; sf[nt][3] = p3;
        }

        #pragma unroll
        for (int kc2 = 0; kc2 < 4; ++kc2) {
            u32 aph[4];
            #pragma unroll
            for (int half_ = 0; half_ < 2; ++half_) {
                float* f = sf[2*kc2 + half_];
                __half2 h0 = __floats2half2_rn(f[0], f[1]);
                __half2 h1 = __floats2half2_rn(f[2], f[3]);
                aph[2*half_]   = *(u32*)&h0;
                aph[2*half_+1] = *(u32*)&h1;
            }
            int vrow = kc2*16 + ((lane >> 3) & 1)*8 + (lane & 7);
            #pragma unroll
            for (int ntv = 0; ntv < 4; ++ntv) {
                int dch  = ntv*16 + (lane >> 4)*8;
                u32 off = vrow*(SP*2) + dch*2;
                u32 b0,b1,b2,b3;
                ldsm4t(b0,b1,b2,b3, sVh+off);
                mma16(oacc[2*ntv],   aph, b0, b1);
                mma16(oacc[2*ntv+1], aph, b2, b3);
            }
        }
        __syncthreads();
    }

    #pragma unroll
    for (int nt = 0; nt < 8; ++nt) {
        int d = nt*8 + (lane & 3)*2;
        size_t i0 = (size_t)(b*Ss + r0)*DM + h*DKh + d;
        size_t i1 = (size_t)(b*Ss + r0 + 8)*DM + h*DKh + d;
        __half2 h0 = __floats2half2_rn(oacc[nt][0], oacc[nt][1]);
        __half2 h1 = __floats2half2_rn(oacc[nt][2], oacc[nt][3]);
        float2 f0 = __half22float2(h0), f1 = __half22float2(h1);
        *(__half2*)&g_oh_h[i0] = h0;
        *(__half2*)&g_oh_h[i1] = h1;
        *(__half2*)&g_oh_l[i0] = __floats2half2_rn(oacc[nt][0]-f0.x, oacc[nt][1]-f0.y);
        *(__half2*)&g_oh_l[i1] = __floats2half2_rn(oacc[nt][2]-f1.x, oacc[nt][3]-f1.y);
    }
}

// ---------------------------------------------------------------------------
// LayerNorm per row of 1024
// ---------------------------------------------------------------------------
__global__ void __launch_bounds__(256)
layernorm(const float* __restrict__ Xin, const float* __restrict__ gamma,
          const float* __restrict__ beta, float* __restrict__ out)
{
    const float* x = Xin + (size_t)blockIdx.x * DM;
    float* o = out + (size_t)blockIdx.x * DM;
    const int tid = threadIdx.x;
    __shared__ float r1[256], r2[256];

    float v[4], s = 0.f, sq = 0.f;
    #pragma unroll
    for (int i = 0; i < 4; ++i) {
        v[i] = x[tid + i * 256];
        s += v[i];
        sq += v[i] * v[i];
    }
    r1[tid] = s; r2[tid] = sq; __syncthreads();
    for (int st = 128; st > 0; st >>= 1) {
        if (tid < st) { r1[tid] += r1[tid + st]; r2[tid] += r2[tid + st]; }
        __syncthreads();
    }
    float mean = r1[0] * (1.0f / DM);
    float var  = r2[0] * (1.0f / DM) - mean * mean;
    float inv = rsqrtf(var + 1e-5f);
    #pragma unroll
    for (int i = 0; i < 4; ++i) {
        int c = tid + i * 256;
        o[c] = (v[i] - mean) * inv * gamma[c] + beta[c];
    }
}

// ---------------------------------------------------------------------------
extern "C" void kernel_launch(void* const* d_in, const int* in_sizes, int n_in,
                              void* d_out, int out_size)
{
    const float* q    = (const float*)d_in[0];
    const float* k    = (const float*)d_in[1];
    const float* v    = (const float*)d_in[2];
    const unsigned char* mask = (const unsigned char*)d_in[3];
    const float* Wq   = (const float*)d_in[4];
    const float* bq   = (const float*)d_in[5];
    const float* Wk   = (const float*)d_in[6];
    const float* bk   = (const float*)d_in[7];
    const float* Wv   = (const float*)d_in[8];
    const float* bv   = (const float*)d_in[9];
    const float* Wo   = (const float*)d_in[10];
    const float* bo   = (const float*)d_in[11];
    const float* ln_g = (const float*)d_in[12];
    const float* ln_b = (const float*)d_in[13];

    float* outp = (float*)d_out;
    float* attn = outp + OUT_ELEMS;

    __half *qi_h,*qi_l,*ki_h,*ki_l,*vi_h,*vi_l;
    __half *wq_h,*wk_h,*wv_h,*wo_h;
    __half *qh_h,*qh_l,*kh_h,*vh_h,*oh_h,*oh_l;
    float *y;
    cudaGetSymbolAddress((void**)&qi_h, g_qi_h); cudaGetSymbolAddress((void**)&qi_l, g_qi_l);
    cudaGetSymbolAddress((void**)&ki_h, g_ki_h); cudaGetSymbolAddress((void**)&ki_l, g_ki_l);
    cudaGetSymbolAddress((void**)&vi_h, g_vi_h); cudaGetSymbolAddress((void**)&vi_l, g_vi_l);
    cudaGetSymbolAddress((void**)&wq_h, g_wq_h);
    cudaGetSymbolAddress((void**)&wk_h, g_wk_h);
    cudaGetSymbolAddress((void**)&wv_h, g_wv_h);
    cudaGetSymbolAddress((void**)&wo_h, g_wo_h);
    cudaGetSymbolAddress((void**)&qh_h, g_qh_h); cudaGetSymbolAddress((void**)&qh_l, g_qh_l);
    cudaGetSymbolAddress((void**)&kh_h, g_kh_h);
    cudaGetSymbolAddress((void**)&vh_h, g_vh_h);
    cudaGetSymbolAddress((void**)&oh_h, g_oh_h); cudaGetSymbolAddress((void**)&oh_l, g_oh_l);
    cudaGetSymbolAddress((void**)&y, g_y);

    static bool init_done = false;
    static cudaStream_t s2;
    static cudaEvent_t evStart, evSplit, evW, evQK, evV;
    const int GEMM_SMEM = 2 * GSTG * 2;   // 61440
    if (!init_done) {
        cudaFuncSetAttribute(gemm_h3, cudaFuncAttributeMaxDynamicSharedMemorySize, GEMM_SMEM);
        cudaFuncSetAttribute(gemm_qk, cudaFuncAttributeMaxDynamicSharedMemorySize, GEMM_SMEM);
        cudaFuncSetAttribute(gemm_v,  cudaFuncAttributeMaxDynamicSharedMemorySize, GEMM_SMEM);
        cudaStreamCreateWithFlags(&s2, cudaStreamNonBlocking);
        cudaEventCreateWithFlags(&evStart, cudaEventDisableTiming);
        cudaEventCreateWithFlags(&evSplit, cudaEventDisableTiming);
        cudaEventCreateWithFlags(&evW,     cudaEventDisableTiming);
        cudaEventCreateWithFlags(&evQK,    cudaEventDisableTiming);
        cudaEventCreateWithFlags(&evV,     cudaEventDisableTiming);
        init_done = true;
    }

    // ---- fork s2 from main ----
    cudaEventRecord(evStart, 0);
    cudaStreamWaitEvent(s2, evStart, 0);

    // s2: weight transpose + mask bits (independent of input splits)
    dim3 gT(DM/32, DM/32, 4), bT(32, 8);
    splitT_w4<<<gT, bT, 0, s2>>>(Wq, wq_h, Wk, wk_h, Wv, wv_h, Wo, wo_h);
    mask_bits<<<(Bb*Ss*32)/256, 256, 0, s2>>>(mask);
    cudaEventRecord(evW, s2);

    // main: input splits
    const int n4 = MTOK * DM / 4;
    dim3 gS(n4 / 256, 3);
    split_f32x3<<<gS, 256>>>(q, qi_h, qi_l, k, ki_h, ki_l, v, vi_h, vi_l);
    cudaEventRecord(evSplit, 0);

    // main: Q+K projections (needs splits + weights)
    cudaStreamWaitEvent(0, evW, 0);
    dim3 gQK(DM/128, MTOK/128, 2);    // 512 CTAs
    gemm_qk<<<gQK, 256, GEMM_SMEM>>>(qi_h, qi_l, ki_h, ki_l,
                                     wq_h, wk_h, bq, bk,
                                     qh_h, qh_l, kh_h);
    cudaEventRecord(evQK, 0);

    // s2: V projection, concurrent with pass1 (needs vi splits + wv)
    cudaStreamWaitEvent(s2, evSplit, 0);
    cudaStreamWaitEvent(s2, evQK, 0);
    dim3 gV(DM/128, MTOK/128);        // 256 CTAs
    gemm_v<<<gV, 256, GEMM_SMEM, s2>>>(vi_h, vi_l, wv_h, bv, vh_h);
    cudaEventRecord(evV, s2);

    // main: pass1 (needs qh, kh, mbits) — overlaps gemm_v
    dim3 gAttn(Ss/256, Bb*Hh);        // 256 CTAs
    attn_pass1<<<gAttn, 512>>>();

    // main: pass2 (needs vh from s2)
    cudaStreamWaitEvent(0, evV, 0);
    attn_pass2<<<gAttn, 512>>>(attn);

    dim3 gProj(DM/128, MTOK/128);
    gemm_h3<<<gProj, 256, GEMM_SMEM>>>(oh_h, oh_l, wo_h, bo, q,
                                       1.0f, nullptr, nullptr, y, MTOK, DM, DM);

    layernorm<<<MTOK, 256>>>(y, ln_g, ln_b, outp);
}

// round 17
// speedup vs baseline: 1.0095x; 1.0095x over previous
#include <cuda_runtime.h>
#include <cuda_fp16.h>
#include <math.h>

// Problem constants
#define Bb 2
#define Ss 2048
#define DM 1024
#define Hh 16
#define DKh 64
#define MTOK (Bb*Ss)                 // 4096
#define NROWS (Bb*Hh*Ss)             // 65536
#define OUT_ELEMS ((size_t)Bb*Ss*DM)

#define SCALE_L2E 0.18033688011112042f   // 0.125 * log2(e)

typedef unsigned int u32;
typedef unsigned short u16;
typedef unsigned long long u64;

// ---------------- device scratch ----------------
__device__ __half g_qi_h[MTOK*DM], g_qi_l[MTOK*DM];
__device__ __half g_ki_h[MTOK*DM], g_ki_l[MTOK*DM];
__device__ __half g_vi_h[MTOK*DM], g_vi_l[MTOK*DM];
__device__ __half g_wq_h[DM*DM];
__device__ __half g_wk_h[DM*DM];
__device__ __half g_wv_h[DM*DM];
__device__ __half g_wo_h[DM*DM];
__device__ __half g_qh_h[MTOK*DM], g_qh_l[MTOK*DM];
__device__ __half g_kh_h[MTOK*DM];
__device__ __half g_vh_h[MTOK*DM];
__device__ __half g_oh_h[MTOK*DM], g_oh_l[MTOK*DM];
__device__ float  g_y[MTOK*DM];
__device__ float  g_rinv[NROWS];
__device__ u64    g_mbits[(size_t)Bb*Ss*(Ss/64)];   // 1 bit per mask byte

// ---------------- helpers ----------------
__device__ __forceinline__ u32 smaddr(const void* p) {
    return (u32)__cvta_generic_to_shared(p);
}
__device__ __forceinline__ void ldsm4(u32& r0, u32& r1, u32& r2, u32& r3, u32 a) {
    asm volatile("ldmatrix.sync.aligned.m8n8.x4.shared.b16 {%0,%1,%2,%3},[%4];"
                 : "=r"(r0), "=r"(r1), "=r"(r2), "=r"(r3) : "r"(a));
}
__device__ __forceinline__ void ldsm4t(u32& r0, u32& r1, u32& r2, u32& r3, u32 a) {
    asm volatile("ldmatrix.sync.aligned.m8n8.x4.trans.shared.b16 {%0,%1,%2,%3},[%4];"
                 : "=r"(r0), "=r"(r1), "=r"(r2), "=r"(r3) : "r"(a));
}
__device__ __forceinline__ void mma16(float* d, const u32* a, u32 b0, u32 b1) {
    asm volatile(
        "mma.sync.aligned.m16n8k16.row.col.f32.f16.f16.f32 "
        "{%0,%1,%2,%3},{%4,%5,%6,%7},{%8,%9},{%0,%1,%2,%3};"
        : "+f"(d[0]), "+f"(d[1]), "+f"(d[2]), "+f"(d[3])
        : "r"(a[0]), "r"(a[1]), "r"(a[2]), "r"(a[3]), "r"(b0), "r"(b1));
}
__device__ __forceinline__ void cpa16(u32 dst, const void* src) {
    asm volatile("cp.async.cg.shared.global [%0], [%1], 16;" :: "r"(dst), "l"(src));
}
#define CP_COMMIT() asm volatile("cp.async.commit_group;")
#define CP_WAIT1()  asm volatile("cp.async.wait_group 1;")
#define CP_WAIT0()  asm volatile("cp.async.wait_group 0;")
__device__ __forceinline__ float ex2f(float x) {
    float r; asm("ex2.approx.f32 %0, %1;" : "=f"(r) : "f"(x)); return r;
}
__device__ __forceinline__ void stcs2(float* p, float x, float y) {
    asm volatile("st.global.cs.v2.f32 [%0], {%1,%2};" :: "l"(p), "f"(x), "f"(y) : "memory");
}

// ---------------- mask -> bitmask (1 bit per byte) ----------------
__global__ void __launch_bounds__(256)
mask_bits(const unsigned char* __restrict__ mask)
{
    int i = blockIdx.x * 256 + threadIdx.x;
    const u64* src = (const u64*)(mask + (size_t)i * 64);
    u64 bits = 0;
    #pragma unroll
    for (int c = 0; c < 8; ++c) {
        u64 w = src[c] & 0x0101010101010101ULL;
        bits |= ((w * 0x0102040810204080ULL) >> 56) << (c * 8);
    }
    g_mbits[i] = bits;
}

// ---------------- merged split kernels ----------------
__global__ void __launch_bounds__(256)
split_f32x3(const float* __restrict__ s0, __half* __restrict__ h0, __half* __restrict__ l0,
            const float* __restrict__ s1, __half* __restrict__ h1, __half* __restrict__ l1,
            const float* __restrict__ s2, __half* __restrict__ h2, __half* __restrict__ l2)
{
    int i = blockIdx.x * 256 + threadIdx.x;
    const float* src; __half* dh; __half* dl;
    if (blockIdx.y == 0)      { src = s0; dh = h0; dl = l0; }
    else if (blockIdx.y == 1) { src = s1; dh = h1; dl = l1; }
    else                      { src = s2; dh = h2; dl = l2; }
    float4 v = ((const float4*)src)[i];
    __half2 a0 = __floats2half2_rn(v.x, v.y);
    __half2 a1 = __floats2half2_rn(v.z, v.w);
    float2 f0 = __half22float2(a0), f1 = __half22float2(a1);
    ((__half2*)dh)[2*i]   = a0; ((__half2*)dh)[2*i+1] = a1;
    ((__half2*)dl)[2*i]   = __floats2half2_rn(v.x - f0.x, v.y - f0.y);
    ((__half2*)dl)[2*i+1] = __floats2half2_rn(v.z - f1.x, v.w - f1.y);
}

__global__ void __launch_bounds__(256)
splitT_w4(const float* __restrict__ W0, __half* __restrict__ th0,
          const float* __restrict__ W1, __half* __restrict__ th1,
          const float* __restrict__ W2, __half* __restrict__ th2,
          const float* __restrict__ W3, __half* __restrict__ th3)
{
    const float* W; __half* th;
    switch (blockIdx.z) {
        case 0:  W = W0; th = th0; break;
        case 1:  W = W1; th = th1; break;
        case 2:  W = W2; th = th2; break;
        default: W = W3; th = th3; break;
    }
    __shared__ float t[32][33];
    int kb = blockIdx.y * 32, nb = blockIdx.x * 32;
    int tx = threadIdx.x, ty = threadIdx.y;
    #pragma unroll
    for (int i = 0; i < 4; ++i)
        t[ty + i*8][tx] = W[(size_t)(kb + ty + i*8) * DM + nb + tx];
    __syncthreads();
    #pragma unroll
    for (int i = 0; i < 4; ++i) {
        int n = nb + ty + i*8, k = kb + tx;
        th[(size_t)n * DM + k] = __float2half_rn(t[tx][ty + i*8]);
    }
}

// ---------------------------------------------------------------------------
// fp16 GEMM core, 2-term, BK=64 stages (half the barriers of BK=32).
// C = (Ah+Al) @ Bh^T (+bias)*omul (+R)
// ---------------------------------------------------------------------------
#define SG 72
#define GARR (128*SG)          // 9216 halves per array
#define GSTG (3*GARR)          // 27648 halves per stage
__device__ __forceinline__ void
gemm_core(const __half* __restrict__ Ah, const __half* __restrict__ Al,
          const __half* __restrict__ Bh,
          const float* __restrict__ bias, const float* __restrict__ R,
          float omul,
          __half* __restrict__ Ch, __half* __restrict__ Cl,
          float* __restrict__ Cf, int M, int N, int K,
          __half* dsm, int bm, int bn)
{
    const int tid = threadIdx.x, lane = tid & 31, wid = tid >> 5;
    const int wm = wid & 3, wn = wid >> 2;
    float acc[2][8][4] = {};
    const int arow = lane & 15, achk = lane >> 4;
    const int brow = ((lane >> 4) << 3) + (lane & 7), bchk = (lane >> 3) & 1;
    const u32 smbase = smaddr(dsm);

    auto load_stage = [&](int st, int k0) {
        u32 base = smbase + (u32)st * GSTG * 2;
        #pragma unroll
        for (int i = 0; i < 4; ++i) {
            int e = tid + i * 256;               // 0..1023
            int m = e >> 3, c = e & 7;           // row, 8-half chunk
            size_t ga = (size_t)(bm + m) * K + k0 + c*8;
            size_t gb = (size_t)(bn + m) * K + k0 + c*8;
            u32 o = (u32)(m*SG + c*8) * 2;
            cpa16(base + 0*GARR*2 + o, Ah + ga);
            cpa16(base + 1*GARR*2 + o, Al + ga);
            cpa16(base + 2*GARR*2 + o, Bh + gb);
        }
        CP_COMMIT();
    };

    const int nk = K / 64;       // 16 iterations
    load_stage(0, 0);
    for (int kt = 0; kt < nk; ++kt) {
        if (kt + 1 < nk) { load_stage((kt+1)&1, (kt+1)*64); CP_WAIT1(); }
        else             { CP_WAIT0(); }
        __syncthreads();
        const u32 sAh = smbase + (u32)(kt&1)*GSTG*2;
        const u32 sAl = sAh + GARR*2;
        const u32 sBh = sAl + GARR*2;
        #pragma unroll
        for (int kc = 0; kc < 4; ++kc) {
            u32 ah[2][4], al[2][4];
            #pragma unroll
            for (int mt = 0; mt < 2; ++mt) {
                int row = wm*32 + mt*16 + arow;
                u32 off = row*(SG*2) + (2*kc + achk)*16;
                ldsm4(ah[mt][0],ah[mt][1],ah[mt][2],ah[mt][3], sAh+off);
                ldsm4(al[mt][0],al[mt][1],al[mt][2],al[mt][3], sAl+off);
            }
            #pragma unroll
            for (int ntp = 0; ntp < 4; ++ntp) {
                int row = wn*64 + ntp*16 + brow;
                u32 off = row*(SG*2) + (2*kc + bchk)*16;
                u32 b0,b1,b2,b3;
                ldsm4(b0,b1,b2,b3, sBh+off);
                mma16(acc[0][2*ntp],   ah[0], b0, b1);
                mma16(acc[1][2*ntp],   ah[1], b0, b1);
                mma16(acc[0][2*ntp+1], ah[0], b2, b3);
                mma16(acc[1][2*ntp+1], ah[1], b2, b3);
                mma16(acc[0][2*ntp],   al[0], b0, b1);
                mma16(acc[1][2*ntp],   al[1], b0, b1);
                mma16(acc[0][2*ntp+1], al[0], b2, b3);
                mma16(acc[1][2*ntp+1], al[1], b2, b3);
            }
        }
        __syncthreads();
    }

    #pragma unroll
    for (int mt = 0; mt < 2; ++mt) {
        int r0 = bm + wm*32 + mt*16 + (lane >> 2);
        #pragma unroll
        for (int nt = 0; nt < 8; ++nt) {
            int n = bn + wn*64 + nt*8 + (lane & 3)*2;
            float2 bs = *(const float2*)&bias[n];
            float* d = acc[mt][nt];
            float v00 = (d[0]+bs.x)*omul, v01 = (d[1]+bs.y)*omul;
            float v10 = (d[2]+bs.x)*omul, v11 = (d[3]+bs.y)*omul;
            if (Cf) {
                float2 ra = *(const float2*)&R[(size_t)r0*N + n];
                float2 rb = *(const float2*)&R[(size_t)(r0+8)*N + n];
                *(float2*)&Cf[(size_t)r0*N + n]     = make_float2(v00+ra.x, v01+ra.y);
                *(float2*)&Cf[(size_t)(r0+8)*N + n] = make_float2(v10+rb.x, v11+rb.y);
            } else if (Cl) {
                __half2 h0 = __floats2half2_rn(v00, v01);
                __half2 h1 = __floats2half2_rn(v10, v11);
                float2 f0 = __half22float2(h0), f1 = __half22float2(h1);
                *(__half2*)&Ch[(size_t)r0*N + n]     = h0;
                *(__half2*)&Ch[(size_t)(r0+8)*N + n] = h1;
                *(__half2*)&Cl[(size_t)r0*N + n]     = __floats2half2_rn(v00-f0.x, v01-f0.y);
                *(__half2*)&Cl[(size_t)(r0+8)*N + n] = __floats2half2_rn(v10-f1.x, v11-f1.y);
            } else {
                *(__half2*)&Ch[(size_t)r0*N + n]     = __floats2half2_rn(v00, v01);
                *(__half2*)&Ch[(size_t)(r0+8)*N + n] = __floats2half2_rn(v10, v11);
            }
        }
    }
}

// Out-projection wrapper
__global__ void __launch_bounds__(256)
gemm_h3(const __half* __restrict__ Ah, const __half* __restrict__ Al,
        const __half* __restrict__ Bh,
        const float* __restrict__ bias, const float* __restrict__ R,
        float omul,
        __half* __restrict__ Ch, __half* __restrict__ Cl,
        float* __restrict__ Cf, int M, int N, int K)
{
    extern __shared__ __half dsm[];
    gemm_core(Ah, Al, Bh, bias, R, omul, Ch, Cl, Cf, M, N, K,
              dsm, blockIdx.y * 128, blockIdx.x * 128);
}

// Fused QKV projections: grid.z = 0(Q) / 1(K) / 2(V)
__global__ void __launch_bounds__(256)
gemm_qkv(const __half* __restrict__ qih, const __half* __restrict__ qil,
         const __half* __restrict__ kih, const __half* __restrict__ kil,
         const __half* __restrict__ vih, const __half* __restrict__ vil,
         const __half* __restrict__ wqh,
         const __half* __restrict__ wkh,
         const __half* __restrict__ wvh,
         const float* __restrict__ bq, const float* __restrict__ bk,
         const float* __restrict__ bv,
         __half* __restrict__ qhh, __half* __restrict__ qhl,
         __half* __restrict__ khh, __half* __restrict__ vhh)
{
    extern __shared__ __half dsm[];
    int bm = blockIdx.y * 128, bn = blockIdx.x * 128;
    if (blockIdx.z == 0)
        gemm_core(qih, qil, wqh, bq, nullptr, SCALE_L2E,
                  qhh, qhl, nullptr, MTOK, DM, DM, dsm, bm, bn);
    else if (blockIdx.z == 1)
        gemm_core(kih, kil, wkh, bk, nullptr, 1.0f,
                  khh, nullptr, nullptr, MTOK, DM, DM, dsm, bm, bn);
    else
        gemm_core(vih, vil, wvh, bv, nullptr, 1.0f,
                  vhh, nullptr, nullptr, MTOK, DM, DM, dsm, bm, bn);
}

// ---------------------------------------------------------------------------
// Pass 1: row sums of 2^(qh.kh) (masked) — normalizer only.
// 256 q-rows per block, 512 threads. K hi-only staging, double-buffered.
// ---------------------------------------------------------------------------
#define SP 72
__global__ void __launch_bounds__(512)
attn_pass1()
{
    __shared__ __half sK[2][64*SP];
    const int tid = threadIdx.x, lane = tid & 31, wid = tid >> 5;
    const int bh = blockIdx.y, b = bh >> 4, h = bh & 15;
    const int bq = blockIdx.x * 256;
    const int arow = lane & 15, achk = lane >> 4;
    const int brow = ((lane >> 4) << 3) + (lane & 7), bchk = (lane >> 3) & 1;

    u32 qfh[4][4];
    #pragma unroll
    for (int c = 0; c < 4; ++c) {
        {
            int m = tid >> 3, ch = tid & 7;
            size_t gq = (size_t)(b*Ss + bq + c*64 + m)*DM + h*DKh + ch*8;
            *(uint4*)&sK[0][m*SP + ch*8] = *(const uint4*)&g_qh_h[gq];
        }
        __syncthreads();
        if ((wid >> 2) == c) {
            int rloc = (wid & 3)*16 + arow;
            #pragma unroll
            for (int kc = 0; kc < 4; ++kc) {
                u32 off = rloc*(SP*2) + (2*kc + achk)*16;
                ldsm4(qfh[kc][0],qfh[kc][1],qfh[kc][2],qfh[kc][3], smaddr(sK[0])+off);
            }
        }
        __syncthreads();
    }

    auto load_stage = [&](int st, int kt) {
        int m = tid >> 3, ch = tid & 7;
        size_t gk = (size_t)(b*Ss + kt*64 + m)*DM + h*DKh + ch*8;
        cpa16(smaddr(sK[st]) + (u32)(m*SP + ch*8)*2, g_kh_h + gk);
        CP_COMMIT();
    };

    const int r0 = bq + wid*16 + (lane >> 2);
    float rs0 = 0.f, rs1 = 0.f;

    load_stage(0, 0);
    for (int kt = 0; kt < 32; ++kt) {
        if (kt + 1 < 32) { load_stage((kt+1)&1, kt+1); CP_WAIT1(); }
        else             { CP_WAIT0(); }
        __syncthreads();
        const u32 sKh = smaddr(sK[kt&1]);

        float sf[8][4] = {};
        #pragma unroll
        for (int kc = 0; kc < 4; ++kc) {
            #pragma unroll
            for (int ntp = 0; ntp < 4; ++ntp) {
                int row = ntp*16 + brow;
                u32 off = row*(SP*2) + (2*kc + bchk)*16;
                u32 b0,b1,b2,b3;
                ldsm4(b0,b1,b2,b3, sKh+off);
                mma16(sf[2*ntp],   qfh[kc], b0, b1);
                mma16(sf[2*ntp+1], qfh[kc], b2, b3);
            }
        }
        u64 mb0 = g_mbits[((size_t)b*Ss + r0)*32 + kt];
        u64 mb1 = g_mbits[((size_t)b*Ss + r0 + 8)*32 + kt];
        #pragma unroll
        for (int nt = 0; nt < 8; ++nt) {
            int sh = nt*8 + (lane & 3)*2;
            if (!((mb0 >> sh)     & 1)) rs0 += ex2f(sf[nt][0]);
            if (!((mb0 >> (sh+1)) & 1)) rs0 += ex2f(sf[nt][1]);
            if (!((mb1 >> sh)     & 1)) rs1 += ex2f(sf[nt][2]);
            if (!((mb1 >> (sh+1)) & 1)) rs1 += ex2f(sf[nt][3]);
        }
        __syncthreads();
    }

    rs0 += __shfl_xor_sync(0xffffffffu, rs0, 1);
    rs0 += __shfl_xor_sync(0xffffffffu, rs0, 2);
    rs1 += __shfl_xor_sync(0xffffffffu, rs1, 1);
    rs1 += __shfl_xor_sync(0xffffffffu, rs1, 2);
    if ((lane & 3) == 0) {
        g_rinv[(size_t)bh*Ss + r0]     = 1.0f / rs0;
        g_rinv[(size_t)bh*Ss + r0 + 8] = 1.0f / rs1;
    }
}

// ---------------------------------------------------------------------------
// Pass 2: S = (qh+ql).kh, p = 2^s*inv -> attn (streaming stores); PV fused.
// ---------------------------------------------------------------------------
__global__ void __launch_bounds__(512)
attn_pass2(float* __restrict__ P)
{
    __shared__ __half sKV[2][2][64*SP];
    const int tid = threadIdx.x, lane = tid & 31, wid = tid >> 5;
    const int bh = blockIdx.y, b = bh >> 4, h = bh & 15;
    const int bq = blockIdx.x * 256;
    const int arow = lane & 15, achk = lane >> 4;
    const int brow = ((lane >> 4) << 3) + (lane & 7), bchk = (lane >> 3) & 1;

    u32 qfh[4][4], qfl[4][4];
    #pragma unroll
    for (int c = 0; c < 4; ++c) {
        {
            int m = tid >> 3, ch = tid & 7;
            size_t gq = (size_t)(b*Ss + bq + c*64 + m)*DM + h*DKh + ch*8;
            *(uint4*)&sKV[0][0][m*SP + ch*8] = *(const uint4*)&g_qh_h[gq];
            *(uint4*)&sKV[0][1][m*SP + ch*8] = *(const uint4*)&g_qh_l[gq];
        }
        __syncthreads();
        if ((wid >> 2) == c) {
            int rloc = (wid & 3)*16 + arow;
            #pragma unroll
            for (int kc = 0; kc < 4; ++kc) {
                u32 off = rloc*(SP*2) + (2*kc + achk)*16;
                ldsm4(qfh[kc][0],qfh[kc][1],qfh[kc][2],qfh[kc][3], smaddr(sKV[0][0])+off);
                ldsm4(qfl[kc][0],qfl[kc][1],qfl[kc][2],qfl[kc][3], smaddr(sKV[0][1])+off);
            }
        }
        __syncthreads();
    }

    auto load_stage = [&](int st, int kt) {
        int m = tid >> 3, ch = tid & 7;
        size_t gk = (size_t)(b*Ss + kt*64 + m)*DM + h*DKh + ch*8;
        u32 o = (u32)(m*SP + ch*8)*2;
        cpa16(smaddr(sKV[st][0]) + o, g_kh_h + gk);
        cpa16(smaddr(sKV[st][1]) + o, g_vh_h + gk);
        CP_COMMIT();
    };

    const int r0 = bq + wid*16 + (lane >> 2);
    const float inv0 = g_rinv[(size_t)bh*Ss + r0];
    const float inv1 = g_rinv[(size_t)bh*Ss + r0 + 8];
    float oacc[8][4] = {};

    load_stage(0, 0);
    for (int kt = 0; kt < 32; ++kt) {
        if (kt + 1 < 32) { load_stage((kt+1)&1, kt+1); CP_WAIT1(); }
        else             { CP_WAIT0(); }
        __syncthreads();
        const u32 sKh = smaddr(sKV[kt&1][0]);
        const u32 sVh = smaddr(sKV[kt&1][1]);

        float sf[8][4] = {};
        #pragma unroll
        for (int kc = 0; kc < 4; ++kc) {
            #pragma unroll
            for (int ntp = 0; ntp < 4; ++ntp) {
                int row = ntp*16 + brow;
                u32 off = row*(SP*2) + (2*kc + bchk)*16;
                u32 b0,b1,b2,b3;
                ldsm4(b0,b1,b2,b3, sKh+off);
                mma16(sf[2*ntp],   qfh[kc], b0, b1);
                mma16(sf[2*ntp+1], qfh[kc], b2, b3);
                mma16(sf[2*ntp],   qfl[kc], b0, b1);
                mma16(sf[2*ntp+1], qfl[kc], b2, b3);
            }
        }

        u64 mb0 = g_mbits[((size_t)b*Ss + r0)*32 + kt];
        u64 mb1 = g_mbits[((size_t)b*Ss + r0 + 8)*32 + kt];
        #pragma unroll
        for (int nt = 0; nt < 8; ++nt) {
            int sh = nt*8 + (lane & 3)*2;
            int col = kt*64 + sh;
            float p0 = ((mb0 >> sh)     & 1) ? 0.f : ex2f(sf[nt][0]) * inv0;
            float p1 = ((mb0 >> (sh+1)) & 1) ? 0.f : ex2f(sf[nt][1]) * inv0;
            float p2 = ((mb1 >> sh)     & 1) ? 0.f : ex2f(sf[nt][2]) * inv1;
            float p3 = ((mb1 >> (sh+1)) & 1) ? 0.f : ex2f(sf[nt][3]) * inv1;
            stcs2(&P[((size_t)bh*Ss + r0)*Ss + col],     p0, p1);
            stcs2(&P[((size_t)bh*Ss + r0 + 8)*Ss + col], p2, p3);
            sf[nt][0] = p0; sf[nt][1] = p1; sf[nt][2] = p2; sf[nt][3] = p3;
        }

        #pragma unroll
        for (int kc2 = 0; kc2 < 4; ++kc2) {
            u32 aph[4];
            #pragma unroll
            for (int half_ = 0; half_ < 2; ++half_) {
                float* f = sf[2*kc2 + half_];
                __half2 h0 = __floats2half2_rn(f[0], f[1]);
                __half2 h1 = __floats2half2_rn(f[2], f[3]);
                aph[2*half_]   = *(u32*)&h0;
                aph[2*half_+1] = *(u32*)&h1;
            }
            int vrow = kc2*16 + ((lane >> 3) & 1)*8 + (lane & 7);
            #pragma unroll
            for (int ntv = 0; ntv < 4; ++ntv) {
                int dch  = ntv*16 + (lane >> 4)*8;
                u32 off = vrow*(SP*2) + dch*2;
                u32 b0,b1,b2,b3;
                ldsm4t(b0,b1,b2,b3, sVh+off);
                mma16(oacc[2*ntv],   aph, b0, b1);
                mma16(oacc[2*ntv+1], aph, b2, b3);
            }
        }
        __syncthreads();
    }

    #pragma unroll
    for (int nt = 0; nt < 8; ++nt) {
        int d = nt*8 + (lane & 3)*2;
        size_t i0 = (size_t)(b*Ss + r0)*DM + h*DKh + d;
        size_t i1 = (size_t)(b*Ss + r0 + 8)*DM + h*DKh + d;
        __half2 h0 = __floats2half2_rn(oacc[nt][0], oacc[nt][1]);
        __half2 h1 = __floats2half2_rn(oacc[nt][2], oacc[nt][3]);
        float2 f0 = __half22float2(h0), f1 = __half22float2(h1);
        *(__half2*)&g_oh_h[i0] = h0;
        *(__half2*)&g_oh_h[i1] = h1;
        *(__half2*)&g_oh_l[i0] = __floats2half2_rn(oacc[nt][0]-f0.x, oacc[nt][1]-f0.y);
        *(__half2*)&g_oh_l[i1] = __floats2half2_rn(oacc[nt][2]-f1.x, oacc[nt][3]-f1.y);
    }
}

// ---------------------------------------------------------------------------
// LayerNorm per row of 1024
// ---------------------------------------------------------------------------
__global__ void __launch_bounds__(256)
layernorm(const float* __restrict__ Xin, const float* __restrict__ gamma,
          const float* __restrict__ beta, float* __restrict__ out)
{
    const float* x = Xin + (size_t)blockIdx.x * DM;
    float* o = out + (size_t)blockIdx.x * DM;
    const int tid = threadIdx.x;
    __shared__ float r1[256], r2[256];

    float v[4], s = 0.f, sq = 0.f;
    #pragma unroll
    for (int i = 0; i < 4; ++i) {
        v[i] = x[tid + i * 256];
        s += v[i];
        sq += v[i] * v[i];
    }
    r1[tid] = s; r2[tid] = sq; __syncthreads();
    for (int st = 128; st > 0; st >>= 1) {
        if (tid < st) { r1[tid] += r1[tid + st]; r2[tid] += r2[tid + st]; }
        __syncthreads();
    }
    float mean = r1[0] * (1.0f / DM);
    float var  = r2[0] * (1.0f / DM) - mean * mean;
    float inv = rsqrtf(var + 1e-5f);
    #pragma unroll
    for (int i = 0; i < 4; ++i) {
        int c = tid + i * 256;
        o[c] = (v[i] - mean) * inv * gamma[c] + beta[c];
    }
}

// ---------------------------------------------------------------------------
extern "C" void kernel_launch(void* const* d_in, const int* in_sizes, int n_in,
                              void* d_out, int out_size)
{
    const float* q    = (const float*)d_in[0];
    const float* k    = (const float*)d_in[1];
    const float* v    = (const float*)d_in[2];
    const unsigned char* mask = (const unsigned char*)d_in[3];
    const float* Wq   = (const float*)d_in[4];
    const float* bq   = (const float*)d_in[5];
    const float* Wk   = (const float*)d_in[6];
    const float* bk   = (const float*)d_in[7];
    const float* Wv   = (const float*)d_in[8];
    const float* bv   = (const float*)d_in[9];
    const float* Wo   = (const float*)d_in[10];
    const float* bo   = (const float*)d_in[11];
    const float* ln_g = (const float*)d_in[12];
    const float* ln_b = (const float*)d_in[13];

    float* outp = (float*)d_out;
    float* attn = outp + OUT_ELEMS;

    __half *qi_h,*qi_l,*ki_h,*ki_l,*vi_h,*vi_l;
    __half *wq_h,*wk_h,*wv_h,*wo_h;
    __half *qh_h,*qh_l,*kh_h,*vh_h,*oh_h,*oh_l;
    float *y;
    cudaGetSymbolAddress((void**)&qi_h, g_qi_h); cudaGetSymbolAddress((void**)&qi_l, g_qi_l);
    cudaGetSymbolAddress((void**)&ki_h, g_ki_h); cudaGetSymbolAddress((void**)&ki_l, g_ki_l);
    cudaGetSymbolAddress((void**)&vi_h, g_vi_h); cudaGetSymbolAddress((void**)&vi_l, g_vi_l);
    cudaGetSymbolAddress((void**)&wq_h, g_wq_h);
    cudaGetSymbolAddress((void**)&wk_h, g_wk_h);
    cudaGetSymbolAddress((void**)&wv_h, g_wv_h);
    cudaGetSymbolAddress((void**)&wo_h, g_wo_h);
    cudaGetSymbolAddress((void**)&qh_h, g_qh_h); cudaGetSymbolAddress((void**)&qh_l, g_qh_l);
    cudaGetSymbolAddress((void**)&kh_h, g_kh_h);
    cudaGetSymbolAddress((void**)&vh_h, g_vh_h);
    cudaGetSymbolAddress((void**)&oh_h, g_oh_h); cudaGetSymbolAddress((void**)&oh_l, g_oh_l);
    cudaGetSymbolAddress((void**)&y, g_y);

    static bool attr_done = false;
    const int GEMM_SMEM = 2 * GSTG * 2;   // 110592 bytes
    if (!attr_done) {
        cudaFuncSetAttribute(gemm_h3,  cudaFuncAttributeMaxDynamicSharedMemorySize, GEMM_SMEM);
        cudaFuncSetAttribute(gemm_qkv, cudaFuncAttributeMaxDynamicSharedMemorySize, GEMM_SMEM);
        attr_done = true;
    }

    const int n4 = MTOK * DM / 4;
    dim3 gS(n4 / 256, 3);
    split_f32x3<<<gS, 256>>>(q, qi_h, qi_l, k, ki_h, ki_l, v, vi_h, vi_l);
    mask_bits<<<(Bb*Ss*32)/256, 256>>>(mask);

    dim3 gT(DM/32, DM/32, 4), bT(32, 8);
    splitT_w4<<<gT, bT>>>(Wq, wq_h, Wk, wk_h, Wv, wv_h, Wo, wo_h);

    dim3 gQKV(DM/128, MTOK/128, 3);   // (8, 32, 3)
    gemm_qkv<<<gQKV, 256, GEMM_SMEM>>>(qi_h, qi_l, ki_h, ki_l, vi_h, vi_l,
                                       wq_h, wk_h, wv_h,
                                       bq, bk, bv,
                                       qh_h, qh_l, kh_h, vh_h);

    dim3 gAttn(Ss/256, Bb*Hh);        // (8, 32)
    attn_pass1<<<gAttn, 512>>>();
    attn_pass2<<<gAttn, 512>>>(attn);

    dim3 gProj(DM/128, MTOK/128);
    gemm_h3<<<gProj, 256, GEMM_SMEM>>>(oh_h, oh_l, wo_h, bo, q,
                                       1.0f, nullptr, nullptr, y, MTOK, DM, DM);

    layernorm<<<MTOK, 256>>>(y, ln_g, ln_b, outp);
}